// round 1
// baseline (speedup 1.0000x reference)
#include <cuda_runtime.h>

// B3-spline undecimated wavelet transform (a trous), 3 levels, fused.
// x: (8, 1024, 1024) f32 -> out: (8, 4, 1024, 1024) f32 = [w1, w2, w3, c3]
//
// Fusion correctness: B3 taps are symmetric; conv of a mirror-extended signal
// with a symmetric kernel stays mirror-symmetric, so reflect-padding at every
// level == one mirror extension of the original input. Hence a tile that loads
// its halo (cumulative radius 14) with a single reflect index map computes all
// three levels exactly.

#define IMG   1024
#define TS    64            // output tile
#define HL    14            // halo: 2*(1+2+4)
#define S     (TS + 2*HL)   // 92 haloed tile extent
#define SP    (S + 1)       // 93 smem row stride (odd -> conflict-free columns)
#define NTHR  256

#define SMEM_BYTES (2 * S * SP * sizeof(float))

__device__ __forceinline__ int reflect_idx(int g) {
    // jnp.pad 'reflect': no edge repeat. |offset| <= 14 < IMG so one fold is enough.
    if (g < 0) g = -g;
    if (g >= IMG) g = 2 * IMG - 2 - g;
    return g;
}

__global__ void __launch_bounds__(NTHR) uwt_kernel(const float* __restrict__ x,
                                                   float* __restrict__ out) {
    extern __shared__ float smem[];
    float* P = smem;             // current c_j (haloed)
    float* Q = smem + S * SP;    // H-conv temp

    const int b   = blockIdx.z;
    const int ty0 = blockIdx.y * TS;   // global row of tile origin (center)
    const int tx0 = blockIdx.x * TS;   // global col of tile origin (center)
    const float* xb = x + (size_t)b * IMG * IMG;

    // ---- load c0 with reflect halo ----
    for (int idx = threadIdx.x; idx < S * S; idx += NTHR) {
        int ly = idx / S;
        int lx = idx - ly * S;
        int gy = reflect_idx(ty0 + ly - HL);
        int gx = reflect_idx(tx0 + lx - HL);
        P[ly * SP + lx] = xb[gy * IMG + gx];
    }
    __syncthreads();

    const float w0 = 0.0625f;  // 1/16
    const float w1 = 0.25f;    // 1/4
    const float w2 = 0.375f;   // 3/8

    int h = 0;  // current valid-halo inset of P
#pragma unroll
    for (int j = 0; j < 3; j++) {
        const int d  = 1 << j;
        const int a  = h + 2 * d;       // inset after this level's conv
        // ---- H conv (along y): rows [a, S-a), cols [h, S-h) ----
        {
            const int rows = S - 2 * a;
            const int cols = S - 2 * h;
            for (int idx = threadIdx.x; idx < rows * cols; idx += NTHR) {
                int ry = idx / cols;
                int rx = idx - ry * cols;
                int y  = a + ry;
                int xx = h + rx;
                int o  = y * SP + xx;
                float v = w2 * P[o]
                        + w1 * (P[o - d * SP]     + P[o + d * SP])
                        + w0 * (P[o - 2 * d * SP] + P[o + 2 * d * SP]);
                Q[o] = v;
            }
        }
        __syncthreads();
        // ---- W conv (along x): rows & cols [a, S-a); write c_j in place,
        //      emit w_{j+1} = c_{j-1} - c_j on the center region ----
        {
            const int n2 = S - 2 * a;
            float* och = out + (((size_t)b * 4 + j) * IMG) * IMG;
            for (int idx = threadIdx.x; idx < n2 * n2; idx += NTHR) {
                int ry = idx / n2;
                int rx = idx - ry * n2;
                int y  = a + ry;
                int xx = a + rx;
                int o  = y * SP + xx;
                float c = w2 * Q[o]
                        + w1 * (Q[o - d]     + Q[o + d])
                        + w0 * (Q[o - 2 * d] + Q[o + 2 * d]);
                float prev = P[o];
                P[o] = c;                      // safe: only this thread touches P[o]
                if (y >= HL && y < S - HL && xx >= HL && xx < S - HL) {
                    int gy = ty0 + y - HL;
                    int gx = tx0 + xx - HL;
                    och[gy * IMG + gx] = prev - c;
                }
            }
        }
        __syncthreads();
        h = a;
    }

    // ---- write c3 (channel 3) ----
    {
        float* och = out + (((size_t)b * 4 + 3) * IMG) * IMG;
        for (int idx = threadIdx.x; idx < TS * TS; idx += NTHR) {
            int ly = idx / TS;
            int lx = idx - ly * TS;
            int y  = HL + ly;
            int xx = HL + lx;
            och[(ty0 + ly) * IMG + (tx0 + lx)] = P[y * SP + xx];
        }
    }
}

extern "C" void kernel_launch(void* const* d_in, const int* in_sizes, int n_in,
                              void* d_out, int out_size) {
    const float* x = (const float*)d_in[0];
    float* out     = (float*)d_out;

    cudaFuncSetAttribute(uwt_kernel, cudaFuncAttributeMaxDynamicSharedMemorySize,
                         (int)SMEM_BYTES);

    dim3 grid(IMG / TS, IMG / TS, 8);   // 16 x 16 x 8 = 2048 CTAs
    uwt_kernel<<<grid, NTHR, SMEM_BYTES>>>(x, out);
}

// round 2
// speedup vs baseline: 1.1024x; 1.1024x over previous
#include <cuda_runtime.h>

// B3-spline undecimated wavelet transform (a trous), 3 levels, fully fused.
// x: (8, 1024, 1024) f32 -> out: (8, 4, 1024, 1024) f32 = [w1, w2, w3, c3]
//
// R2: register-blocked passes. H-conv = 4-row strips with contiguous register
// window (8/12/20 scalar LDS per 4 outputs). W-conv = 4-col groups via LDS.128
// window loads; SHIFT=2 column offset makes all float4 accesses 16B-aligned
// (insets a ∈ {2,6,14} are all ≡ 2 mod 4). w_j / c3 written with STG.128.

#define IMG   1024
#define TS    64
#define HL    14
#define S     (TS + 2*HL)   // 92
#define SP    96            // row stride (16B-aligned rows)
#define NTHR  256
#define SHIFT 2             // phys col = logical col + SHIFT

#define SMEM_FLOATS (2 * S * SP + 8)
#define SMEM_BYTES  (SMEM_FLOATS * sizeof(float))

__device__ __forceinline__ int reflect_idx(int g) {
    if (g < 0) g = -g;
    if (g >= IMG) g = 2 * IMG - 2 - g;
    return g;
}

template<int d, int h, int a>
__device__ __forceinline__ void do_level(float* __restrict__ P,
                                         float* __restrict__ Q,
                                         float* __restrict__ och,
                                         int ty0, int tx0) {
    const float w0 = 0.0625f, w1 = 0.25f, w2 = 0.375f;

    // ---- H-conv (along y): P -> Q. rows [a, S-a), cols [h, S-h). 4-row strips.
    {
        constexpr int rows = S - 2 * a;      // 88 / 80 / 64
        constexpr int cols = S - 2 * h;      // 92 / 88 / 80
        constexpr int yt   = rows / 4;
        for (int idx = threadIdx.x; idx < yt * cols; idx += NTHR) {
            int x  = idx % cols;
            int t  = idx / cols;
            int y0 = a + 4 * t;
            int oc = h + x + SHIFT;
            int ob = (y0 - 2 * d) * SP + oc;
            float v[4 * d + 4];
#pragma unroll
            for (int i = 0; i < 4 * d + 4; i++) v[i] = P[ob + i * SP];
#pragma unroll
            for (int i = 0; i < 4; i++) {
                Q[(y0 + i) * SP + oc] = w2 * v[2 * d + i]
                                      + w1 * (v[d + i] + v[3 * d + i])
                                      + w0 * (v[i] + v[4 * d + i]);
            }
        }
    }
    __syncthreads();

    // ---- W-conv (along x): Q -> P (in place), emit w_j on center. 4-col groups.
    {
        constexpr int n2  = S - 2 * a;                     // 88 / 80 / 64
        constexpr int xg  = n2 / 4;                        // 22 / 20 / 16
        constexpr int off = ((a - 2 * d) + SHIFT) & 3;     // 2 / 0 / 0
        constexpr int nw  = (4 * d + 4 + off + 3) & ~3;    // 12 / 12 / 20
        for (int idx = threadIdx.x; idx < n2 * xg; idx += NTHR) {
            int g  = idx % xg;
            int y  = a + idx / xg;
            int x0 = a + 4 * g;                 // logical
            int op = y * SP + x0 + SHIFT;       // phys, 16B-aligned
            int ow = op - 2 * d - off;          // aligned window start
            float v[nw];
#pragma unroll
            for (int k = 0; k < nw / 4; k++) {
                float4 t4 = *reinterpret_cast<const float4*>(&Q[ow + 4 * k]);
                v[4 * k] = t4.x; v[4 * k + 1] = t4.y;
                v[4 * k + 2] = t4.z; v[4 * k + 3] = t4.w;
            }
            float4 prev = *reinterpret_cast<const float4*>(&P[op]);
            float c[4];
#pragma unroll
            for (int i = 0; i < 4; i++) {
                c[i] = w2 * v[off + 2 * d + i]
                     + w1 * (v[off + d + i] + v[off + 3 * d + i])
                     + w0 * (v[off + i] + v[off + 4 * d + i]);
            }
            *reinterpret_cast<float4*>(&P[op]) = make_float4(c[0], c[1], c[2], c[3]);
            // center-group test: group grid aligns with [HL, S-HL) boundaries
            bool center = (a == HL) ||
                          (y >= HL && y < S - HL && x0 >= HL && x0 < S - HL);
            if (center) {
                int gy = ty0 + y - HL;
                int gx = tx0 + x0 - HL;
                *reinterpret_cast<float4*>(&och[gy * IMG + gx]) =
                    make_float4(prev.x - c[0], prev.y - c[1],
                                prev.z - c[2], prev.w - c[3]);
            }
        }
    }
    __syncthreads();
}

__global__ void __launch_bounds__(NTHR) uwt_kernel(const float* __restrict__ x,
                                                   float* __restrict__ out) {
    extern __shared__ float smem[];
    float* P = smem;
    float* Q = smem + S * SP + 4;

    const int b   = blockIdx.z;
    const int ty0 = blockIdx.y * TS;
    const int tx0 = blockIdx.x * TS;
    const float* xb = x + (size_t)b * IMG * IMG;

    // ---- load c0 with reflect halo (phys col = lx + SHIFT) ----
    for (int idx = threadIdx.x; idx < S * S; idx += NTHR) {
        int ly = idx / S;
        int lx = idx - ly * S;
        int gy = reflect_idx(ty0 + ly - HL);
        int gx = reflect_idx(tx0 + lx - HL);
        P[ly * SP + lx + SHIFT] = xb[gy * IMG + gx];
    }
    __syncthreads();

    float* ob = out + (size_t)b * 4 * IMG * IMG;
    do_level<1, 0, 2> (P, Q, ob + 0 * IMG * IMG, ty0, tx0);
    do_level<2, 2, 6> (P, Q, ob + 1 * IMG * IMG, ty0, tx0);
    do_level<4, 6, 14>(P, Q, ob + 2 * IMG * IMG, ty0, tx0);

    // ---- write c3 (channel 3), vectorized ----
    {
        float* och = ob + 3 * IMG * IMG;
        constexpr int gpr = TS / 4;   // 16 groups per row
        for (int idx = threadIdx.x; idx < TS * gpr; idx += NTHR) {
            int g  = idx % gpr;
            int ly = idx / gpr;
            int pc = (HL + ly) * SP + HL + 4 * g + SHIFT;   // 16B-aligned
            float4 v = *reinterpret_cast<const float4*>(&P[pc]);
            *reinterpret_cast<float4*>(&och[(ty0 + ly) * IMG + tx0 + 4 * g]) = v;
        }
    }
}

extern "C" void kernel_launch(void* const* d_in, const int* in_sizes, int n_in,
                              void* d_out, int out_size) {
    const float* x = (const float*)d_in[0];
    float* out     = (float*)d_out;

    cudaFuncSetAttribute(uwt_kernel, cudaFuncAttributeMaxDynamicSharedMemorySize,
                         (int)SMEM_BYTES);

    dim3 grid(IMG / TS, IMG / TS, 8);
    uwt_kernel<<<grid, NTHR, SMEM_BYTES>>>(x, out);
}

// round 3
// speedup vs baseline: 1.2236x; 1.1099x over previous
#include <cuda_runtime.h>

// B3-spline undecimated wavelet transform (a trous), 3 levels, fully fused.
// x: (8, 1024, 1024) f32 -> out: (8, 4, 1024, 1024) f32 = [w1, w2, w3, c3]
//
// R3: 512 threads/CTA (48 warps/SM at 3 CTAs) to hide LDS/barrier latency.
// H-conv: register-window strips (d=1,2), accumulator form (d=4, low live regs).
// W-conv: float4 window loads; d=4 taps align exactly to float4 lanes.

#define IMG   1024
#define TS    64
#define HL    14
#define S     (TS + 2*HL)   // 92
#define SP    96            // row stride (16B-aligned rows)
#define NTHR  512
#define SHIFT 2             // phys col = logical col + SHIFT

#define SMEM_FLOATS (2 * S * SP + 8)
#define SMEM_BYTES  (SMEM_FLOATS * sizeof(float))

__device__ __forceinline__ int reflect_idx(int g) {
    if (g < 0) g = -g;
    if (g >= IMG) g = 2 * IMG - 2 - g;
    return g;
}

__device__ __forceinline__ float4 f4_add(float4 a, float4 b) {
    return make_float4(a.x + b.x, a.y + b.y, a.z + b.z, a.w + b.w);
}

template<int d, int h, int a>
__device__ __forceinline__ void do_level(float* __restrict__ P,
                                         float* __restrict__ Q,
                                         float* __restrict__ och,
                                         int ty0, int tx0) {
    const float w0 = 0.0625f, w1 = 0.25f, w2 = 0.375f;

    // ---- H-conv (along y): P -> Q. rows [a, S-a), cols [h, S-h). 4-row strips.
    {
        constexpr int rows = S - 2 * a;      // 88 / 80 / 64
        constexpr int cols = S - 2 * h;      // 92 / 88 / 80
        constexpr int yt   = rows / 4;
        for (int idx = threadIdx.x; idx < yt * cols; idx += NTHR) {
            int x  = idx % cols;
            int t  = idx / cols;
            int y0 = a + 4 * t;
            int oc = h + x + SHIFT;
            if constexpr (d < 4) {
                int ob = (y0 - 2 * d) * SP + oc;
                float v[4 * d + 4];
#pragma unroll
                for (int i = 0; i < 4 * d + 4; i++) v[i] = P[ob + i * SP];
#pragma unroll
                for (int i = 0; i < 4; i++) {
                    Q[(y0 + i) * SP + oc] = w2 * v[2 * d + i]
                                          + w1 * (v[d + i] + v[3 * d + i])
                                          + w0 * (v[i] + v[4 * d + i]);
                }
            } else {
                // accumulator form: 20 distinct rows, ~6 live regs
                float c0 = 0.f, c1 = 0.f, c2 = 0.f, c3 = 0.f;
                const float wk[5] = {w0, w1, w2, w1, w0};
#pragma unroll
                for (int k = 0; k < 5; k++) {
                    int base = (y0 + (k - 2) * d) * SP + oc;
                    c0 += wk[k] * P[base];
                    c1 += wk[k] * P[base + SP];
                    c2 += wk[k] * P[base + 2 * SP];
                    c3 += wk[k] * P[base + 3 * SP];
                }
                Q[y0 * SP + oc]           = c0;
                Q[(y0 + 1) * SP + oc]     = c1;
                Q[(y0 + 2) * SP + oc]     = c2;
                Q[(y0 + 3) * SP + oc]     = c3;
            }
        }
    }
    __syncthreads();

    // ---- W-conv (along x): Q -> P (in place), emit w_j on center. 4-col groups.
    {
        constexpr int n2  = S - 2 * a;                     // 88 / 80 / 64
        constexpr int xg  = n2 / 4;                        // 22 / 20 / 16
        for (int idx = threadIdx.x; idx < n2 * xg; idx += NTHR) {
            int g  = idx % xg;
            int y  = a + idx / xg;
            int x0 = a + 4 * g;                 // logical
            int op = y * SP + x0 + SHIFT;       // phys, 16B-aligned
            float c0, c1, c2, c3;
            if constexpr (d == 4) {
                // taps land exactly on float4 lanes
                float4 A = *reinterpret_cast<const float4*>(&Q[op - 8]);
                float4 B = *reinterpret_cast<const float4*>(&Q[op - 4]);
                float4 C = *reinterpret_cast<const float4*>(&Q[op]);
                float4 D = *reinterpret_cast<const float4*>(&Q[op + 4]);
                float4 E = *reinterpret_cast<const float4*>(&Q[op + 8]);
                float4 AE = f4_add(A, E), BD = f4_add(B, D);
                c0 = w0 * AE.x + w1 * BD.x + w2 * C.x;
                c1 = w0 * AE.y + w1 * BD.y + w2 * C.y;
                c2 = w0 * AE.z + w1 * BD.z + w2 * C.z;
                c3 = w0 * AE.w + w1 * BD.w + w2 * C.w;
            } else {
                constexpr int off = ((a - 2 * d) + SHIFT) & 3;   // 2 (d=1), 0 (d=2)
                constexpr int nw  = (4 * d + 4 + off + 3) & ~3;  // 12 / 12
                int ow = op - 2 * d - off;                        // aligned
                float v[nw];
#pragma unroll
                for (int k = 0; k < nw / 4; k++) {
                    float4 t4 = *reinterpret_cast<const float4*>(&Q[ow + 4 * k]);
                    v[4 * k] = t4.x; v[4 * k + 1] = t4.y;
                    v[4 * k + 2] = t4.z; v[4 * k + 3] = t4.w;
                }
                c0 = w2 * v[off + 2 * d]     + w1 * (v[off + d]     + v[off + 3 * d])
                   + w0 * (v[off]            + v[off + 4 * d]);
                c1 = w2 * v[off + 2 * d + 1] + w1 * (v[off + d + 1] + v[off + 3 * d + 1])
                   + w0 * (v[off + 1]        + v[off + 4 * d + 1]);
                c2 = w2 * v[off + 2 * d + 2] + w1 * (v[off + d + 2] + v[off + 3 * d + 2])
                   + w0 * (v[off + 2]        + v[off + 4 * d + 2]);
                c3 = w2 * v[off + 2 * d + 3] + w1 * (v[off + d + 3] + v[off + 3 * d + 3])
                   + w0 * (v[off + 3]        + v[off + 4 * d + 3]);
            }
            float4 prev = *reinterpret_cast<const float4*>(&P[op]);
            *reinterpret_cast<float4*>(&P[op]) = make_float4(c0, c1, c2, c3);
            bool center = (a == HL) ||
                          (y >= HL && y < S - HL && x0 >= HL && x0 < S - HL);
            if (center) {
                int gy = ty0 + y - HL;
                int gx = tx0 + x0 - HL;
                *reinterpret_cast<float4*>(&och[gy * IMG + gx]) =
                    make_float4(prev.x - c0, prev.y - c1,
                                prev.z - c2, prev.w - c3);
            }
        }
    }
    __syncthreads();
}

__global__ void __launch_bounds__(NTHR, 3) uwt_kernel(const float* __restrict__ x,
                                                      float* __restrict__ out) {
    extern __shared__ float smem[];
    float* P = smem;
    float* Q = smem + S * SP + 4;

    const int b   = blockIdx.z;
    const int ty0 = blockIdx.y * TS;
    const int tx0 = blockIdx.x * TS;
    const float* xb = x + (size_t)b * IMG * IMG;

    // ---- load c0 with reflect halo (phys col = lx + SHIFT) ----
    for (int idx = threadIdx.x; idx < S * S; idx += NTHR) {
        int ly = idx / S;
        int lx = idx - ly * S;
        int gy = reflect_idx(ty0 + ly - HL);
        int gx = reflect_idx(tx0 + lx - HL);
        P[ly * SP + lx + SHIFT] = xb[gy * IMG + gx];
    }
    __syncthreads();

    float* ob = out + (size_t)b * 4 * IMG * IMG;
    do_level<1, 0, 2> (P, Q, ob + 0 * IMG * IMG, ty0, tx0);
    do_level<2, 2, 6> (P, Q, ob + 1 * IMG * IMG, ty0, tx0);
    do_level<4, 6, 14>(P, Q, ob + 2 * IMG * IMG, ty0, tx0);

    // ---- write c3 (channel 3), vectorized ----
    {
        float* och = ob + 3 * IMG * IMG;
        constexpr int gpr = TS / 4;   // 16 groups per row
        for (int idx = threadIdx.x; idx < TS * gpr; idx += NTHR) {
            int g  = idx % gpr;
            int ly = idx / gpr;
            int pc = (HL + ly) * SP + HL + 4 * g + SHIFT;   // 16B-aligned
            float4 v = *reinterpret_cast<const float4*>(&P[pc]);
            *reinterpret_cast<float4*>(&och[(ty0 + ly) * IMG + tx0 + 4 * g]) = v;
        }
    }
}

extern "C" void kernel_launch(void* const* d_in, const int* in_sizes, int n_in,
                              void* d_out, int out_size) {
    const float* x = (const float*)d_in[0];
    float* out     = (float*)d_out;

    cudaFuncSetAttribute(uwt_kernel, cudaFuncAttributeMaxDynamicSharedMemorySize,
                         (int)SMEM_BYTES);

    dim3 grid(IMG / TS, IMG / TS, 8);
    uwt_kernel<<<grid, NTHR, SMEM_BYTES>>>(x, out);
}